// round 15
// baseline (speedup 1.0000x reference)
#include <cuda_runtime.h>
#include <cuda_fp16.h>
#include <cstdint>

#define NNODES 10000
#define NEDGES 160000
#define BATCH  32
#define FIN    64
#define KPOLY  5
#define FOUT   128
#define NPOOL  (NNODES / 4)
#define TERM_SZ ((size_t)BATCH * NNODES * FIN)
#define H2PAIRS (TERM_SZ / 2)

// ---------------- static device scratch (no allocations allowed) ----------------
__device__ __half  g_Th[4 * (size_t)BATCH * NNODES * FIN];// fp16 terms T1..T4
__device__ __half  g_xh[(size_t)BATCH * NNODES * FIN];    // fp16 copy of x (= T0)
__device__ __half  g_Wh[KPOLY * FOUT * FIN];              // W^T in half: [k][fo][f]
__device__ int   g_count[NNODES];
__device__ int   g_cursor[NNODES];
__device__ int   g_row_start[NNODES + 1];
__device__ int2  g_csr[NEDGES];                           // packed (col, val-bits)

// ---------------- fused prep: zero counts + W^T half cvt + x half cvt -----------
__global__ __launch_bounds__(256) void k_prep(const float* __restrict__ x,
                                              const float* __restrict__ W) {
    size_t i = (size_t)blockIdx.x * 256 + threadIdx.x;
    if (i < H2PAIRS) {
        float2 f = ((const float2*)x)[i];
        ((__half2*)g_xh)[i] = __floats2half2_rn(f.x, f.y);
    }
    if (i < NNODES) g_count[i] = 0;
    if (i < (size_t)(KPOLY * FOUT * FIN)) {
        int k = (int)i / (FOUT * FIN);
        int r = (int)i - k * FOUT * FIN;
        int fo = r / FIN;
        int f = r - fo * FIN;
        g_Wh[i] = __float2half(W[(f * KPOLY + k) * FOUT + fo]);
    }
}

// ---------------- CSR build: histogram -> scan -> permuting scatter -------------
__global__ void k_count(const int* __restrict__ rows) {
    int e = blockIdx.x * blockDim.x + threadIdx.x;
    if (e < NEDGES) atomicAdd(&g_count[rows[e]], 1);
}
__global__ void k_scan() {
    const int T = 256;
    const int PER = (NNODES + T - 1) / T;
    int t = threadIdx.x;
    int base = t * PER;
    int sum = 0;
    for (int i = 0; i < PER; i++) {
        int idx = base + i;
        if (idx < NNODES) sum += g_count[idx];
    }
    __shared__ int sc[T];
    sc[t] = sum;
    __syncthreads();
    for (int d = 1; d < T; d <<= 1) {
        int v = (t >= d) ? sc[t - d] : 0;
        __syncthreads();
        sc[t] += v;
        __syncthreads();
    }
    int run = sc[t] - sum;
    for (int i = 0; i < PER; i++) {
        int idx = base + i;
        if (idx < NNODES) {
            g_row_start[idx] = run;
            g_cursor[idx] = run;
            run += g_count[idx];
        }
    }
    if (t == T - 1) g_row_start[NNODES] = run;
}
__global__ void k_scatter(const int* __restrict__ rows, const int* __restrict__ cols,
                          const float* __restrict__ vals) {
    int e = blockIdx.x * blockDim.x + threadIdx.x;
    if (e < NEDGES) {
        int r = rows[e];
        int p = atomicAdd(&g_cursor[r], 1);
        g_csr[p] = make_int2(cols[e], __float_as_int(vals[e]));
    }
}

// ---------------- gather SpMM (Chebyshev step), all-fp16, LDG.64 gathers --------
__global__ __launch_bounds__(256) void k_spmm(int in_t, int out_t, int prev_t) {
    int r = blockIdx.x;                 // node row
    int grp = threadIdx.x >> 5;         // 0..7
    int lane = threadIdx.x & 31;
    int pairSel = lane >> 4;
    int quad = lane & 15;

    int b0 = grp + pairSel * 8;
    int b1 = grp + (2 + pairSel) * 8;
    const size_t ROWU = 16;
    size_t pb0 = (size_t)b0 * NNODES * ROWU;
    size_t pb1 = (size_t)b1 * NNODES * ROWU;

    const uint2* srcU = (const uint2*)((in_t < 0) ? g_xh
                          : g_Th + (size_t)in_t * TERM_SZ);

    int s = g_row_start[r];
    int e = g_row_start[r + 1];
    float4 a0 = make_float4(0.f, 0.f, 0.f, 0.f);
    float4 a1 = make_float4(0.f, 0.f, 0.f, 0.f);

    int j = s;
    for (; j + 3 < e; j += 4) {
        size_t off[4];
        float v[4];
#pragma unroll
        for (int u = 0; u < 4; u++) {
            int2 cv = g_csr[j + u];
            off[u] = (size_t)cv.x * ROWU + quad;
            v[u] = __int_as_float(cv.y);
        }
        uint2 h0[4], h1[4];
#pragma unroll
        for (int u = 0; u < 4; u++) {
            h0[u] = __ldg(srcU + pb0 + off[u]);
            h1[u] = __ldg(srcU + pb1 + off[u]);
        }
#pragma unroll
        for (int u = 0; u < 4; u++) {
            float2 f0a = __half22float2(*(const __half2*)&h0[u].x);
            float2 f0b = __half22float2(*(const __half2*)&h0[u].y);
            float2 f1a = __half22float2(*(const __half2*)&h1[u].x);
            float2 f1b = __half22float2(*(const __half2*)&h1[u].y);
            a0.x = fmaf(v[u], f0a.x, a0.x); a0.y = fmaf(v[u], f0a.y, a0.y);
            a0.z = fmaf(v[u], f0b.x, a0.z); a0.w = fmaf(v[u], f0b.y, a0.w);
            a1.x = fmaf(v[u], f1a.x, a1.x); a1.y = fmaf(v[u], f1a.y, a1.y);
            a1.z = fmaf(v[u], f1b.x, a1.z); a1.w = fmaf(v[u], f1b.y, a1.w);
        }
    }
    for (; j < e; j++) {
        int2 cv = g_csr[j];
        size_t o = (size_t)cv.x * ROWU + quad;
        float v = __int_as_float(cv.y);
        uint2 h0 = __ldg(srcU + pb0 + o);
        uint2 h1 = __ldg(srcU + pb1 + o);
        float2 f0a = __half22float2(*(const __half2*)&h0.x);
        float2 f0b = __half22float2(*(const __half2*)&h0.y);
        float2 f1a = __half22float2(*(const __half2*)&h1.x);
        float2 f1b = __half22float2(*(const __half2*)&h1.y);
        a0.x = fmaf(v, f0a.x, a0.x); a0.y = fmaf(v, f0a.y, a0.y);
        a0.z = fmaf(v, f0b.x, a0.z); a0.w = fmaf(v, f0b.y, a0.w);
        a1.x = fmaf(v, f1a.x, a1.x); a1.y = fmaf(v, f1a.y, a1.y);
        a1.z = fmaf(v, f1b.x, a1.z); a1.w = fmaf(v, f1b.y, a1.w);
    }

    size_t o0 = pb0 + (size_t)r * ROWU + quad;
    size_t o1 = pb1 + (size_t)r * ROWU + quad;
    if (prev_t >= -1) {
        const uint2* Tp = (const uint2*)((prev_t < 0) ? g_xh
                            : g_Th + (size_t)prev_t * TERM_SZ);
        uint2 p0 = __ldg(Tp + o0);
        uint2 p1 = __ldg(Tp + o1);
        float2 q0a = __half22float2(*(const __half2*)&p0.x);
        float2 q0b = __half22float2(*(const __half2*)&p0.y);
        float2 q1a = __half22float2(*(const __half2*)&p1.x);
        float2 q1b = __half22float2(*(const __half2*)&p1.y);
        a0.x = 2.f * a0.x - q0a.x; a0.y = 2.f * a0.y - q0a.y;
        a0.z = 2.f * a0.z - q0b.x; a0.w = 2.f * a0.w - q0b.y;
        a1.x = 2.f * a1.x - q1a.x; a1.y = 2.f * a1.y - q1a.y;
        a1.z = 2.f * a1.z - q1b.x; a1.w = 2.f * a1.w - q1b.y;
    }
    uint2* dst = (uint2*)(g_Th + (size_t)out_t * TERM_SZ);
    uint2 w0, w1;
    *(__half2*)&w0.x = __floats2half2_rn(a0.x, a0.y);
    *(__half2*)&w0.y = __floats2half2_rn(a0.z, a0.w);
    *(__half2*)&w1.x = __floats2half2_rn(a1.x, a1.y);
    *(__half2*)&w1.y = __floats2half2_rn(a1.z, a1.w);
    dst[o0] = w0;
    dst[o1] = w1;
}

// ---------------- fp16 mma projection + bias + ReLU + maxpool4 ------------------
// CTA: 128 nodes x 128 fo, 16 warps (8 M x 2 N), warp tile 16x64, 512 threads.
// Halved warp tile -> acc = 32 regs/thread -> NO spills (R14's 2-CTA cap forced
// ~48 spilled regs and cancelled the occupancy gain). 16 warps/SM with zero
// spill tax. A double-buffered cp.async; B via LDG.128->STS (L1-cached).
#define HSTR 72
#define STAGE_BYTES (128 * HSTR * 2)
#define SMEM_BYTES  (4 * STAGE_BYTES)                // 73728

__device__ __forceinline__ void mma_f16(float* d, const uint32_t* a,
                                        uint32_t b0, uint32_t b1) {
    asm volatile(
        "mma.sync.aligned.m16n8k16.row.col.f32.f16.f16.f32 "
        "{%0,%1,%2,%3}, {%4,%5,%6,%7}, {%8,%9}, {%0,%1,%2,%3};"
        : "+f"(d[0]), "+f"(d[1]), "+f"(d[2]), "+f"(d[3])
        : "r"(a[0]), "r"(a[1]), "r"(a[2]), "r"(a[3]), "r"(b0), "r"(b1));
}

__device__ __forceinline__ void ldsm_x4(uint32_t& r0, uint32_t& r1,
                                        uint32_t& r2, uint32_t& r3, uint32_t addr) {
    asm volatile("ldmatrix.sync.aligned.m8n8.x4.shared.b16 {%0,%1,%2,%3}, [%4];"
                 : "=r"(r0), "=r"(r1), "=r"(r2), "=r"(r3) : "r"(addr));
}

__device__ __forceinline__ uint32_t smem_u32(const void* p) {
    uint32_t a;
    asm("{ .reg .u64 t; cvta.to.shared.u64 t, %1; cvt.u32.u64 %0, t; }"
        : "=r"(a) : "l"(p));
    return a;
}

// 1024 16B ops spread over 512 threads (2 iterations)
__device__ __forceinline__ void load_A(__half* dst, const __half* __restrict__ src,
                                       int max_rows) {
    int t = threadIdx.x;
#pragma unroll
    for (int i = 0; i < 2; i++) {
        int q = t + 512 * i;
        int row = q >> 3;
        int f4 = q & 7;
        uint32_t daddr;
        asm("{ .reg .u64 tt; cvta.to.shared.u64 tt, %1; cvt.u32.u64 %0, tt; }"
            : "=r"(daddr) : "l"(dst + row * HSTR + f4 * 8));
        int sz = (row < max_rows) ? 16 : 0;
        asm volatile("cp.async.cg.shared.global [%0], [%1], 16, %2;"
                     :: "r"(daddr), "l"(src + (size_t)row * FIN + f4 * 8), "r"(sz));
    }
}

__device__ __forceinline__ void load_B(__half* dst, const __half* __restrict__ src) {
    int t = threadIdx.x;
#pragma unroll
    for (int i = 0; i < 2; i++) {
        int q = t + 512 * i;
        int row = q >> 3;
        int f4 = q & 7;
        uint4 v = *(const uint4*)(src + (size_t)row * FIN + f4 * 8);
        *(uint4*)(dst + row * HSTR + f4 * 8) = v;
    }
}

__global__ __launch_bounds__(512, 1) void k_gemm(const float* __restrict__ bias,
                                                 float* __restrict__ out) {
    extern __shared__ __half sm[];
    __half* As[2] = { sm,                 sm + 2 * 128 * HSTR };
    __half* Bs[2] = { sm + 128 * HSTR,    sm + 3 * 128 * HSTR };

    int tid = threadIdx.x;
    int wid = tid >> 5, lane = tid & 31;
    int wm = wid >> 1, wn = wid & 1;          // 8 M-warps x 2 N-warps
    int g = lane >> 2, q = lane & 3;
    int b = blockIdx.y;
    int n0 = blockIdx.x * 128;
    int max_rows = NNODES - n0;

    int a_row = lane & 15;
    int a_koff = (lane & 16) ? 8 : 0;
    int b_row = (lane & 7) + ((lane & 16) ? 8 : 0);
    int b_koff = (lane & 8) ? 8 : 0;

    float acc[8][4];
#pragma unroll
    for (int nt = 0; nt < 8; nt++)
#pragma unroll
        for (int i = 0; i < 4; i++) acc[nt][i] = 0.f;

    const __half* terms[KPOLY];
    terms[0] = g_xh + ((size_t)b * NNODES + n0) * FIN;
#pragma unroll
    for (int kk = 1; kk < KPOLY; kk++)
        terms[kk] = g_Th + (size_t)(kk - 1) * TERM_SZ + ((size_t)b * NNODES + n0) * FIN;

    load_A(As[0], terms[0], max_rows);
    asm volatile("cp.async.commit_group;" ::: "memory");
    load_B(Bs[0], g_Wh);

#pragma unroll
    for (int c = 0; c < KPOLY; c++) {
        int st = c & 1;
        if (c + 1 < KPOLY) {
            load_A(As[st ^ 1], terms[c + 1], max_rows);
            asm volatile("cp.async.commit_group;" ::: "memory");
            load_B(Bs[st ^ 1], g_Wh + (size_t)(c + 1) * FOUT * FIN);
            asm volatile("cp.async.wait_group 1;" ::: "memory");
        } else {
            asm volatile("cp.async.wait_group 0;" ::: "memory");
        }
        __syncthreads();

        uint32_t abase = smem_u32(As[st]);
        uint32_t bbase = smem_u32(Bs[st]);
#pragma unroll
        for (int k16 = 0; k16 < 4; k16++) {
            int kb = k16 * 16;
            uint32_t af[4];
            {
                uint32_t addr = abase +
                    2u * ((wm * 16 + a_row) * HSTR + kb + a_koff);
                ldsm_x4(af[0], af[1], af[2], af[3], addr);
            }
#pragma unroll
            for (int gt = 0; gt < 4; gt++) {
                uint32_t addr = bbase +
                    2u * ((wn * 64 + gt * 16 + b_row) * HSTR + kb + b_koff);
                uint32_t b0, b1, b2, b3;
                ldsm_x4(b0, b1, b2, b3, addr);
                mma_f16(acc[2 * gt],     af, b0, b1);
                mma_f16(acc[2 * gt + 1], af, b2, b3);
            }
        }
        __syncthreads();
    }

    // epilogue: bias + ReLU, maxpool-4 over fragment rows via 2x shfl, pooled stores
#pragma unroll
    for (int half = 0; half < 2; half++) {
        int nodebase = n0 + wm * 16 + half * 8 + g;
        float res[8][2];
#pragma unroll
        for (int nt = 0; nt < 8; nt++) {
            int col = wn * 64 + nt * 8 + 2 * q;
            float v0 = fmaxf(acc[nt][half * 2 + 0] + __ldg(bias + col), 0.f);
            float v1 = fmaxf(acc[nt][half * 2 + 1] + __ldg(bias + col + 1), 0.f);
            v0 = fmaxf(v0, __shfl_xor_sync(0xffffffffu, v0, 4));
            v0 = fmaxf(v0, __shfl_xor_sync(0xffffffffu, v0, 8));
            v1 = fmaxf(v1, __shfl_xor_sync(0xffffffffu, v1, 4));
            v1 = fmaxf(v1, __shfl_xor_sync(0xffffffffu, v1, 8));
            res[nt][0] = v0;
            res[nt][1] = v1;
        }
        if ((g & 3) == 0 && nodebase < NNODES) {
            float* op = out + ((size_t)b * NPOOL + (nodebase >> 2)) * FOUT;
#pragma unroll
            for (int nt = 0; nt < 8; nt++) {
                int col = wn * 64 + nt * 8 + 2 * q;
                *(float2*)(op + col) = make_float2(res[nt][0], res[nt][1]);
            }
        }
    }
}

// ---------------- launch ---------------------------------------------------------
extern "C" void kernel_launch(void* const* d_in, const int* in_sizes, int n_in,
                              void* d_out, int out_size) {
    const float* x    = (const float*)d_in[0];
    const int*   rows = (const int*)d_in[1];
    const int*   cols = (const int*)d_in[2];
    const float* vals = (const float*)d_in[3];
    const float* W    = (const float*)d_in[4];
    const float* bias = (const float*)d_in[5];
    float* out = (float*)d_out;

    cudaFuncSetAttribute(k_gemm, cudaFuncAttributeMaxDynamicSharedMemorySize, SMEM_BYTES);

    // fused prep (zero counts + W^T/x half cvt), then CSR build
    k_prep<<<(int)((H2PAIRS + 255) / 256), 256>>>(x, W);
    k_count<<<(NEDGES + 255) / 256, 256>>>(rows);
    k_scan<<<1, 256>>>();
    k_scatter<<<(NEDGES + 255) / 256, 256>>>(rows, cols, vals);

    // Chebyshev recurrence: T1 = L x ; Tk = 2 L T(k-1) - T(k-2)
    k_spmm<<<NNODES, 256>>>(-1, 0, -2);
    k_spmm<<<NNODES, 256>>>( 0, 1, -1);
    k_spmm<<<NNODES, 256>>>( 1, 2,  0);
    k_spmm<<<NNODES, 256>>>( 2, 3,  1);

    // fp16 tensor-core projection + fused epilogue (16 warps, spill-free)
    dim3 grid((NNODES + 127) / 128, BATCH);
    k_gemm<<<grid, 512, SMEM_BYTES>>>(bias, out);
}

// round 16
// speedup vs baseline: 1.0583x; 1.0583x over previous
#include <cuda_runtime.h>
#include <cuda_fp16.h>
#include <cstdint>

#define NNODES 10000
#define NEDGES 160000
#define BATCH  32
#define FIN    64
#define KPOLY  5
#define FOUT   128
#define NPOOL  (NNODES / 4)
#define TERM_SZ ((size_t)BATCH * NNODES * FIN)
#define H2PAIRS (TERM_SZ / 2)

// ---------------- static device scratch (no allocations allowed) ----------------
__device__ __half  g_Th[4 * (size_t)BATCH * NNODES * FIN];// fp16 terms T1..T4
__device__ __half  g_xh[(size_t)BATCH * NNODES * FIN];    // fp16 copy of x (= T0)
__device__ __half  g_Wh[KPOLY * FOUT * FIN];              // W^T in half: [k][fo][f]
__device__ int   g_count[NNODES];
__device__ int   g_cursor[NNODES];
__device__ int   g_row_start[NNODES + 1];
__device__ int2  g_csr[NEDGES];                           // packed (col, val-bits)

// ---------------- fused prep: zero counts + W^T half cvt + x half cvt -----------
__global__ __launch_bounds__(256) void k_prep(const float* __restrict__ x,
                                              const float* __restrict__ W) {
    size_t i = (size_t)blockIdx.x * 256 + threadIdx.x;
    if (i < H2PAIRS) {
        float2 f = ((const float2*)x)[i];
        ((__half2*)g_xh)[i] = __floats2half2_rn(f.x, f.y);
    }
    if (i < NNODES) g_count[i] = 0;
    if (i < (size_t)(KPOLY * FOUT * FIN)) {
        int k = (int)i / (FOUT * FIN);
        int r = (int)i - k * FOUT * FIN;
        int fo = r / FIN;
        int f = r - fo * FIN;
        g_Wh[i] = __float2half(W[(f * KPOLY + k) * FOUT + fo]);
    }
}

// ---------------- CSR build: histogram -> scan -> permuting scatter -------------
__global__ void k_count(const int* __restrict__ rows) {
    int e = blockIdx.x * blockDim.x + threadIdx.x;
    if (e < NEDGES) atomicAdd(&g_count[rows[e]], 1);
}
__global__ void k_scan() {
    const int T = 256;
    const int PER = (NNODES + T - 1) / T;
    int t = threadIdx.x;
    int base = t * PER;
    int sum = 0;
    for (int i = 0; i < PER; i++) {
        int idx = base + i;
        if (idx < NNODES) sum += g_count[idx];
    }
    __shared__ int sc[T];
    sc[t] = sum;
    __syncthreads();
    for (int d = 1; d < T; d <<= 1) {
        int v = (t >= d) ? sc[t - d] : 0;
        __syncthreads();
        sc[t] += v;
        __syncthreads();
    }
    int run = sc[t] - sum;
    for (int i = 0; i < PER; i++) {
        int idx = base + i;
        if (idx < NNODES) {
            g_row_start[idx] = run;
            g_cursor[idx] = run;
            run += g_count[idx];
        }
    }
    if (t == T - 1) g_row_start[NNODES] = run;
}
__global__ void k_scatter(const int* __restrict__ rows, const int* __restrict__ cols,
                          const float* __restrict__ vals) {
    int e = blockIdx.x * blockDim.x + threadIdx.x;
    if (e < NEDGES) {
        int r = rows[e];
        int p = atomicAdd(&g_cursor[r], 1);
        g_csr[p] = make_int2(cols[e], __float_as_int(vals[e]));
    }
}

// ---------------- gather SpMM (Chebyshev step), all-fp16, LDG.64 gathers --------
__global__ __launch_bounds__(256) void k_spmm(int in_t, int out_t, int prev_t) {
    int r = blockIdx.x;                 // node row
    int grp = threadIdx.x >> 5;         // 0..7
    int lane = threadIdx.x & 31;
    int pairSel = lane >> 4;
    int quad = lane & 15;

    int b0 = grp + pairSel * 8;
    int b1 = grp + (2 + pairSel) * 8;
    const size_t ROWU = 16;
    size_t pb0 = (size_t)b0 * NNODES * ROWU;
    size_t pb1 = (size_t)b1 * NNODES * ROWU;

    const uint2* srcU = (const uint2*)((in_t < 0) ? g_xh
                          : g_Th + (size_t)in_t * TERM_SZ);

    int s = g_row_start[r];
    int e = g_row_start[r + 1];
    float4 a0 = make_float4(0.f, 0.f, 0.f, 0.f);
    float4 a1 = make_float4(0.f, 0.f, 0.f, 0.f);

    int j = s;
    for (; j + 3 < e; j += 4) {
        size_t off[4];
        float v[4];
#pragma unroll
        for (int u = 0; u < 4; u++) {
            int2 cv = g_csr[j + u];
            off[u] = (size_t)cv.x * ROWU + quad;
            v[u] = __int_as_float(cv.y);
        }
        uint2 h0[4], h1[4];
#pragma unroll
        for (int u = 0; u < 4; u++) {
            h0[u] = __ldg(srcU + pb0 + off[u]);
            h1[u] = __ldg(srcU + pb1 + off[u]);
        }
#pragma unroll
        for (int u = 0; u < 4; u++) {
            float2 f0a = __half22float2(*(const __half2*)&h0[u].x);
            float2 f0b = __half22float2(*(const __half2*)&h0[u].y);
            float2 f1a = __half22float2(*(const __half2*)&h1[u].x);
            float2 f1b = __half22float2(*(const __half2*)&h1[u].y);
            a0.x = fmaf(v[u], f0a.x, a0.x); a0.y = fmaf(v[u], f0a.y, a0.y);
            a0.z = fmaf(v[u], f0b.x, a0.z); a0.w = fmaf(v[u], f0b.y, a0.w);
            a1.x = fmaf(v[u], f1a.x, a1.x); a1.y = fmaf(v[u], f1a.y, a1.y);
            a1.z = fmaf(v[u], f1b.x, a1.z); a1.w = fmaf(v[u], f1b.y, a1.w);
        }
    }
    for (; j < e; j++) {
        int2 cv = g_csr[j];
        size_t o = (size_t)cv.x * ROWU + quad;
        float v = __int_as_float(cv.y);
        uint2 h0 = __ldg(srcU + pb0 + o);
        uint2 h1 = __ldg(srcU + pb1 + o);
        float2 f0a = __half22float2(*(const __half2*)&h0.x);
        float2 f0b = __half22float2(*(const __half2*)&h0.y);
        float2 f1a = __half22float2(*(const __half2*)&h1.x);
        float2 f1b = __half22float2(*(const __half2*)&h1.y);
        a0.x = fmaf(v, f0a.x, a0.x); a0.y = fmaf(v, f0a.y, a0.y);
        a0.z = fmaf(v, f0b.x, a0.z); a0.w = fmaf(v, f0b.y, a0.w);
        a1.x = fmaf(v, f1a.x, a1.x); a1.y = fmaf(v, f1a.y, a1.y);
        a1.z = fmaf(v, f1b.x, a1.z); a1.w = fmaf(v, f1b.y, a1.w);
    }

    size_t o0 = pb0 + (size_t)r * ROWU + quad;
    size_t o1 = pb1 + (size_t)r * ROWU + quad;
    if (prev_t >= -1) {
        const uint2* Tp = (const uint2*)((prev_t < 0) ? g_xh
                            : g_Th + (size_t)prev_t * TERM_SZ);
        uint2 p0 = __ldg(Tp + o0);
        uint2 p1 = __ldg(Tp + o1);
        float2 q0a = __half22float2(*(const __half2*)&p0.x);
        float2 q0b = __half22float2(*(const __half2*)&p0.y);
        float2 q1a = __half22float2(*(const __half2*)&p1.x);
        float2 q1b = __half22float2(*(const __half2*)&p1.y);
        a0.x = 2.f * a0.x - q0a.x; a0.y = 2.f * a0.y - q0a.y;
        a0.z = 2.f * a0.z - q0b.x; a0.w = 2.f * a0.w - q0b.y;
        a1.x = 2.f * a1.x - q1a.x; a1.y = 2.f * a1.y - q1a.y;
        a1.z = 2.f * a1.z - q1b.x; a1.w = 2.f * a1.w - q1b.y;
    }
    uint2* dst = (uint2*)(g_Th + (size_t)out_t * TERM_SZ);
    uint2 w0, w1;
    *(__half2*)&w0.x = __floats2half2_rn(a0.x, a0.y);
    *(__half2*)&w0.y = __floats2half2_rn(a0.z, a0.w);
    *(__half2*)&w1.x = __floats2half2_rn(a1.x, a1.y);
    *(__half2*)&w1.y = __floats2half2_rn(a1.z, a1.w);
    dst[o0] = w0;
    dst[o1] = w1;
}

// ---------------- fp16 mma projection + bias + ReLU + maxpool4 ------------------
// CTA tile 128 nodes x 64 fo, 256 threads, 8 warps (4M x 2N), warp tile 32x32:
// acc = 32 regs/thread -> total ~90 regs -> SPILL-FREE 2 CTAs/SM (the R14 cap
// spilled ~48 regs and cancelled its occupancy gain; R12 profile showed 1-CTA
// phase serialization: tensor 40.7%, DRAM 27%, both half-idle).
// Grid (79 node-tiles, 2 fo-halves, 32 batches): the fo-half pair re-reads A,
// but second read L2-hits (GEMM L2 was only 16.8% busy); DRAM stays 205 MB.
// A double-buffered cp.async; B (W^T half, L1-resident) via LDG.128 -> STS.
#define HSTR 72
#define A_STAGE (128 * HSTR)                         // halves per A stage
#define B_STAGE (64 * HSTR)                          // halves per B stage
#define SMEM_BYTES ((2 * A_STAGE + 2 * B_STAGE) * 2) // 55296; 2 CTAs = 110 KB

__device__ __forceinline__ void mma_f16(float* d, const uint32_t* a,
                                        uint32_t b0, uint32_t b1) {
    asm volatile(
        "mma.sync.aligned.m16n8k16.row.col.f32.f16.f16.f32 "
        "{%0,%1,%2,%3}, {%4,%5,%6,%7}, {%8,%9}, {%0,%1,%2,%3};"
        : "+f"(d[0]), "+f"(d[1]), "+f"(d[2]), "+f"(d[3])
        : "r"(a[0]), "r"(a[1]), "r"(a[2]), "r"(a[3]), "r"(b0), "r"(b1));
}

__device__ __forceinline__ void ldsm_x4(uint32_t& r0, uint32_t& r1,
                                        uint32_t& r2, uint32_t& r3, uint32_t addr) {
    asm volatile("ldmatrix.sync.aligned.m8n8.x4.shared.b16 {%0,%1,%2,%3}, [%4];"
                 : "=r"(r0), "=r"(r1), "=r"(r2), "=r"(r3) : "r"(addr));
}

__device__ __forceinline__ uint32_t smem_u32(const void* p) {
    uint32_t a;
    asm("{ .reg .u64 t; cvta.to.shared.u64 t, %1; cvt.u32.u64 %0, t; }"
        : "=r"(a) : "l"(p));
    return a;
}

// A: 128 rows x 64 half -> 1024 16B cp.async over 256 threads
__device__ __forceinline__ void load_A(__half* dst, const __half* __restrict__ src,
                                       int max_rows) {
    int t = threadIdx.x;
#pragma unroll
    for (int i = 0; i < 4; i++) {
        int q = t + 256 * i;
        int row = q >> 3;
        int f4 = q & 7;
        uint32_t daddr;
        asm("{ .reg .u64 tt; cvta.to.shared.u64 tt, %1; cvt.u32.u64 %0, tt; }"
            : "=r"(daddr) : "l"(dst + row * HSTR + f4 * 8));
        int sz = (row < max_rows) ? 16 : 0;
        asm volatile("cp.async.cg.shared.global [%0], [%1], 16, %2;"
                     :: "r"(daddr), "l"(src + (size_t)row * FIN + f4 * 8), "r"(sz));
    }
}

// B: 64 rows x 64 half via LDG.128 (L1-cached) + STS: 512 16B ops
__device__ __forceinline__ void load_B(__half* dst, const __half* __restrict__ src) {
    int t = threadIdx.x;
#pragma unroll
    for (int i = 0; i < 2; i++) {
        int q = t + 256 * i;
        int row = q >> 3;
        int f4 = q & 7;
        uint4 v = *(const uint4*)(src + (size_t)row * FIN + f4 * 8);
        *(uint4*)(dst + row * HSTR + f4 * 8) = v;
    }
}

__global__ __launch_bounds__(256, 2) void k_gemm(const float* __restrict__ bias,
                                                 float* __restrict__ out) {
    extern __shared__ __half sm[];
    __half* As[2] = { sm,               sm + A_STAGE };
    __half* Bs[2] = { sm + 2 * A_STAGE, sm + 2 * A_STAGE + B_STAGE };

    int tid = threadIdx.x;
    int wid = tid >> 5, lane = tid & 31;
    int wm = wid >> 1, wn = wid & 1;          // 4 M-warps x 2 N-warps
    int g = lane >> 2, q = lane & 3;
    int b = blockIdx.z;
    int n0 = blockIdx.x * 128;
    int fo0 = blockIdx.y * 64;                 // this CTA's fo half
    int max_rows = NNODES - n0;

    int a_row = lane & 15;
    int a_koff = (lane & 16) ? 8 : 0;
    int b_row = (lane & 7) + ((lane & 16) ? 8 : 0);
    int b_koff = (lane & 8) ? 8 : 0;

    float acc[2][4][4];
#pragma unroll
    for (int mt = 0; mt < 2; mt++)
#pragma unroll
        for (int nt = 0; nt < 4; nt++)
#pragma unroll
            for (int i = 0; i < 4; i++) acc[mt][nt][i] = 0.f;

    const __half* terms[KPOLY];
    terms[0] = g_xh + ((size_t)b * NNODES + n0) * FIN;
#pragma unroll
    for (int kk = 1; kk < KPOLY; kk++)
        terms[kk] = g_Th + (size_t)(kk - 1) * TERM_SZ + ((size_t)b * NNODES + n0) * FIN;
    const __half* Wbase = g_Wh + (size_t)fo0 * FIN;

    load_A(As[0], terms[0], max_rows);
    asm volatile("cp.async.commit_group;" ::: "memory");
    load_B(Bs[0], Wbase);

#pragma unroll
    for (int c = 0; c < KPOLY; c++) {
        int st = c & 1;
        if (c + 1 < KPOLY) {
            load_A(As[st ^ 1], terms[c + 1], max_rows);
            asm volatile("cp.async.commit_group;" ::: "memory");
            load_B(Bs[st ^ 1], Wbase + (size_t)(c + 1) * FOUT * FIN);
            asm volatile("cp.async.wait_group 1;" ::: "memory");
        } else {
            asm volatile("cp.async.wait_group 0;" ::: "memory");
        }
        __syncthreads();

        uint32_t abase = smem_u32(As[st]);
        uint32_t bbase = smem_u32(Bs[st]);
#pragma unroll
        for (int k16 = 0; k16 < 4; k16++) {
            int kb = k16 * 16;
            uint32_t af[2][4];
#pragma unroll
            for (int mt = 0; mt < 2; mt++) {
                uint32_t addr = abase +
                    2u * ((wm * 32 + mt * 16 + a_row) * HSTR + kb + a_koff);
                ldsm_x4(af[mt][0], af[mt][1], af[mt][2], af[mt][3], addr);
            }
#pragma unroll
            for (int gt = 0; gt < 2; gt++) {
                uint32_t addr = bbase +
                    2u * ((wn * 32 + gt * 16 + b_row) * HSTR + kb + b_koff);
                uint32_t b0, b1, b2, b3;
                ldsm_x4(b0, b1, b2, b3, addr);
                mma_f16(acc[0][2 * gt],     af[0], b0, b1);
                mma_f16(acc[1][2 * gt],     af[1], b0, b1);
                mma_f16(acc[0][2 * gt + 1], af[0], b2, b3);
                mma_f16(acc[1][2 * gt + 1], af[1], b2, b3);
            }
        }
        __syncthreads();
    }

    // epilogue: bias + ReLU, maxpool-4 over fragment rows via 2x shfl, pooled stores
#pragma unroll
    for (int mt = 0; mt < 2; mt++) {
#pragma unroll
        for (int half = 0; half < 2; half++) {
            int nodebase = n0 + wm * 32 + mt * 16 + half * 8 + g;
            float res[4][2];
#pragma unroll
            for (int nt = 0; nt < 4; nt++) {
                int col = fo0 + wn * 32 + nt * 8 + 2 * q;
                float v0 = fmaxf(acc[mt][nt][half * 2 + 0] + __ldg(bias + col), 0.f);
                float v1 = fmaxf(acc[mt][nt][half * 2 + 1] + __ldg(bias + col + 1), 0.f);
                v0 = fmaxf(v0, __shfl_xor_sync(0xffffffffu, v0, 4));
                v0 = fmaxf(v0, __shfl_xor_sync(0xffffffffu, v0, 8));
                v1 = fmaxf(v1, __shfl_xor_sync(0xffffffffu, v1, 4));
                v1 = fmaxf(v1, __shfl_xor_sync(0xffffffffu, v1, 8));
                res[nt][0] = v0;
                res[nt][1] = v1;
            }
            if ((g & 3) == 0 && nodebase < NNODES) {
                float* op = out + ((size_t)b * NPOOL + (nodebase >> 2)) * FOUT;
#pragma unroll
                for (int nt = 0; nt < 4; nt++) {
                    int col = fo0 + wn * 32 + nt * 8 + 2 * q;
                    *(float2*)(op + col) = make_float2(res[nt][0], res[nt][1]);
                }
            }
        }
    }
}

// ---------------- launch ---------------------------------------------------------
extern "C" void kernel_launch(void* const* d_in, const int* in_sizes, int n_in,
                              void* d_out, int out_size) {
    const float* x    = (const float*)d_in[0];
    const int*   rows = (const int*)d_in[1];
    const int*   cols = (const int*)d_in[2];
    const float* vals = (const float*)d_in[3];
    const float* W    = (const float*)d_in[4];
    const float* bias = (const float*)d_in[5];
    float* out = (float*)d_out;

    cudaFuncSetAttribute(k_gemm, cudaFuncAttributeMaxDynamicSharedMemorySize, SMEM_BYTES);

    // fused prep (zero counts + W^T/x half cvt), then CSR build
    k_prep<<<(int)((H2PAIRS + 255) / 256), 256>>>(x, W);
    k_count<<<(NEDGES + 255) / 256, 256>>>(rows);
    k_scan<<<1, 256>>>();
    k_scatter<<<(NEDGES + 255) / 256, 256>>>(rows, cols, vals);

    // Chebyshev recurrence: T1 = L x ; Tk = 2 L T(k-1) - T(k-2)
    k_spmm<<<NNODES, 256>>>(-1, 0, -2);
    k_spmm<<<NNODES, 256>>>( 0, 1, -1);
    k_spmm<<<NNODES, 256>>>( 1, 2,  0);
    k_spmm<<<NNODES, 256>>>( 2, 3,  1);

    // fp16 tensor-core projection + fused epilogue (128x64 tiles, 2 CTAs/SM)
    dim3 grid((NNODES + 127) / 128, 2, BATCH);
    k_gemm<<<grid, 256, SMEM_BYTES>>>(bias, out);
}

// round 17
// speedup vs baseline: 1.1065x; 1.0455x over previous
#include <cuda_runtime.h>
#include <cuda_fp16.h>
#include <cstdint>

#define NNODES 10000
#define NEDGES 160000
#define BATCH  32
#define FIN    64
#define KPOLY  5
#define FOUT   128
#define NPOOL  (NNODES / 4)
#define TERM_SZ ((size_t)BATCH * NNODES * FIN)
#define H2PAIRS (TERM_SZ / 2)

// ---------------- static device scratch (no allocations allowed) ----------------
__device__ __half  g_Th[4 * (size_t)BATCH * NNODES * FIN];// fp16 terms T1..T4
__device__ __half  g_xh[(size_t)BATCH * NNODES * FIN];    // fp16 copy of x (= T0)
__device__ __half  g_Wh[KPOLY * FOUT * FIN];              // W^T in half: [k][fo][f]
__device__ int   g_count[NNODES];   // ZERO at entry: zero-init at load, re-zeroed by k_scan
__device__ int   g_cursor[NNODES];
__device__ int   g_row_start[NNODES + 1];
__device__ int2  g_csr[NEDGES];                           // packed (col, val-bits)

// ---------------- fused prep: x half cvt + W^T half cvt + edge histogram --------
// g_count is guaranteed zero at entry (load-time zero-init on call 1; k_scan
// re-zeroes it after consumption on every call), so the histogram fuses here
// and rides free under the memory-bound x conversion.
__global__ __launch_bounds__(256) void k_prep(const float* __restrict__ x,
                                              const float* __restrict__ W,
                                              const int* __restrict__ rows) {
    size_t i = (size_t)blockIdx.x * 256 + threadIdx.x;
    if (i < H2PAIRS) {
        float2 f = ((const float2*)x)[i];
        ((__half2*)g_xh)[i] = __floats2half2_rn(f.x, f.y);
    }
    if (i < NEDGES) atomicAdd(&g_count[rows[i]], 1);
    if (i < (size_t)(KPOLY * FOUT * FIN)) {
        int k = (int)i / (FOUT * FIN);
        int r = (int)i - k * FOUT * FIN;
        int fo = r / FIN;
        int f = r - fo * FIN;
        g_Wh[i] = __float2half(W[(f * KPOLY + k) * FOUT + fo]);
    }
}

// ---------------- CSR scan (single block) + count reset -------------------------
__global__ void k_scan() {
    const int T = 256;
    const int PER = (NNODES + T - 1) / T;
    int t = threadIdx.x;
    int base = t * PER;
    int sum = 0;
    int cnt[PER];
    for (int i = 0; i < PER; i++) {
        int idx = base + i;
        cnt[i] = (idx < NNODES) ? g_count[idx] : 0;
        sum += cnt[i];
    }
    __shared__ int sc[T];
    sc[t] = sum;
    __syncthreads();
    for (int d = 1; d < T; d <<= 1) {
        int v = (t >= d) ? sc[t - d] : 0;
        __syncthreads();
        sc[t] += v;
        __syncthreads();
    }
    int run = sc[t] - sum;
    for (int i = 0; i < PER; i++) {
        int idx = base + i;
        if (idx < NNODES) {
            g_row_start[idx] = run;
            g_cursor[idx] = run;
            run += cnt[i];
            g_count[idx] = 0;        // restore zero-invariant for next call's k_prep
        }
    }
    if (t == T - 1) g_row_start[NNODES] = run;
}
__global__ void k_scatter(const int* __restrict__ rows, const int* __restrict__ cols,
                          const float* __restrict__ vals) {
    int e = blockIdx.x * blockDim.x + threadIdx.x;
    if (e < NEDGES) {
        int r = rows[e];
        int p = atomicAdd(&g_cursor[r], 1);
        g_csr[p] = make_int2(cols[e], __float_as_int(vals[e]));
    }
}

// ---------------- gather SpMM (Chebyshev step), all-fp16, LDG.64 gathers --------
__global__ __launch_bounds__(256) void k_spmm(int in_t, int out_t, int prev_t) {
    int r = blockIdx.x;                 // node row
    int grp = threadIdx.x >> 5;         // 0..7
    int lane = threadIdx.x & 31;
    int pairSel = lane >> 4;
    int quad = lane & 15;

    int b0 = grp + pairSel * 8;
    int b1 = grp + (2 + pairSel) * 8;
    const size_t ROWU = 16;
    size_t pb0 = (size_t)b0 * NNODES * ROWU;
    size_t pb1 = (size_t)b1 * NNODES * ROWU;

    const uint2* srcU = (const uint2*)((in_t < 0) ? g_xh
                          : g_Th + (size_t)in_t * TERM_SZ);

    int s = g_row_start[r];
    int e = g_row_start[r + 1];
    float4 a0 = make_float4(0.f, 0.f, 0.f, 0.f);
    float4 a1 = make_float4(0.f, 0.f, 0.f, 0.f);

    int j = s;
    for (; j + 3 < e; j += 4) {
        size_t off[4];
        float v[4];
#pragma unroll
        for (int u = 0; u < 4; u++) {
            int2 cv = g_csr[j + u];
            off[u] = (size_t)cv.x * ROWU + quad;
            v[u] = __int_as_float(cv.y);
        }
        uint2 h0[4], h1[4];
#pragma unroll
        for (int u = 0; u < 4; u++) {
            h0[u] = __ldg(srcU + pb0 + off[u]);
            h1[u] = __ldg(srcU + pb1 + off[u]);
        }
#pragma unroll
        for (int u = 0; u < 4; u++) {
            float2 f0a = __half22float2(*(const __half2*)&h0[u].x);
            float2 f0b = __half22float2(*(const __half2*)&h0[u].y);
            float2 f1a = __half22float2(*(const __half2*)&h1[u].x);
            float2 f1b = __half22float2(*(const __half2*)&h1[u].y);
            a0.x = fmaf(v[u], f0a.x, a0.x); a0.y = fmaf(v[u], f0a.y, a0.y);
            a0.z = fmaf(v[u], f0b.x, a0.z); a0.w = fmaf(v[u], f0b.y, a0.w);
            a1.x = fmaf(v[u], f1a.x, a1.x); a1.y = fmaf(v[u], f1a.y, a1.y);
            a1.z = fmaf(v[u], f1b.x, a1.z); a1.w = fmaf(v[u], f1b.y, a1.w);
        }
    }
    for (; j < e; j++) {
        int2 cv = g_csr[j];
        size_t o = (size_t)cv.x * ROWU + quad;
        float v = __int_as_float(cv.y);
        uint2 h0 = __ldg(srcU + pb0 + o);
        uint2 h1 = __ldg(srcU + pb1 + o);
        float2 f0a = __half22float2(*(const __half2*)&h0.x);
        float2 f0b = __half22float2(*(const __half2*)&h0.y);
        float2 f1a = __half22float2(*(const __half2*)&h1.x);
        float2 f1b = __half22float2(*(const __half2*)&h1.y);
        a0.x = fmaf(v, f0a.x, a0.x); a0.y = fmaf(v, f0a.y, a0.y);
        a0.z = fmaf(v, f0b.x, a0.z); a0.w = fmaf(v, f0b.y, a0.w);
        a1.x = fmaf(v, f1a.x, a1.x); a1.y = fmaf(v, f1a.y, a1.y);
        a1.z = fmaf(v, f1b.x, a1.z); a1.w = fmaf(v, f1b.y, a1.w);
    }

    size_t o0 = pb0 + (size_t)r * ROWU + quad;
    size_t o1 = pb1 + (size_t)r * ROWU + quad;
    if (prev_t >= -1) {
        const uint2* Tp = (const uint2*)((prev_t < 0) ? g_xh
                            : g_Th + (size_t)prev_t * TERM_SZ);
        uint2 p0 = __ldg(Tp + o0);
        uint2 p1 = __ldg(Tp + o1);
        float2 q0a = __half22float2(*(const __half2*)&p0.x);
        float2 q0b = __half22float2(*(const __half2*)&p0.y);
        float2 q1a = __half22float2(*(const __half2*)&p1.x);
        float2 q1b = __half22float2(*(const __half2*)&p1.y);
        a0.x = 2.f * a0.x - q0a.x; a0.y = 2.f * a0.y - q0a.y;
        a0.z = 2.f * a0.z - q0b.x; a0.w = 2.f * a0.w - q0b.y;
        a1.x = 2.f * a1.x - q1a.x; a1.y = 2.f * a1.y - q1a.y;
        a1.z = 2.f * a1.z - q1b.x; a1.w = 2.f * a1.w - q1b.y;
    }
    uint2* dst = (uint2*)(g_Th + (size_t)out_t * TERM_SZ);
    uint2 w0, w1;
    *(__half2*)&w0.x = __floats2half2_rn(a0.x, a0.y);
    *(__half2*)&w0.y = __floats2half2_rn(a0.z, a0.w);
    *(__half2*)&w1.x = __floats2half2_rn(a1.x, a1.y);
    *(__half2*)&w1.y = __floats2half2_rn(a1.z, a1.w);
    dst[o0] = w0;
    dst[o1] = w1;
}

// ---------------- fp16 mma projection + bias + ReLU + maxpool4 ------------------
// R14 GEMM variant (best measured): 128x128 tile, 8 warps, warp tile 32x64,
// double-buffered cp.async A, L1-cached B, __launch_bounds__(256, 2).
#define HSTR 72
#define STAGE_BYTES (128 * HSTR * 2)
#define SMEM_BYTES  (4 * STAGE_BYTES)                // 73728

__device__ __forceinline__ void mma_f16(float* d, const uint32_t* a,
                                        uint32_t b0, uint32_t b1) {
    asm volatile(
        "mma.sync.aligned.m16n8k16.row.col.f32.f16.f16.f32 "
        "{%0,%1,%2,%3}, {%4,%5,%6,%7}, {%8,%9}, {%0,%1,%2,%3};"
        : "+f"(d[0]), "+f"(d[1]), "+f"(d[2]), "+f"(d[3])
        : "r"(a[0]), "r"(a[1]), "r"(a[2]), "r"(a[3]), "r"(b0), "r"(b1));
}

__device__ __forceinline__ void ldsm_x4(uint32_t& r0, uint32_t& r1,
                                        uint32_t& r2, uint32_t& r3, uint32_t addr) {
    asm volatile("ldmatrix.sync.aligned.m8n8.x4.shared.b16 {%0,%1,%2,%3}, [%4];"
                 : "=r"(r0), "=r"(r1), "=r"(r2), "=r"(r3) : "r"(addr));
}

__device__ __forceinline__ uint32_t smem_u32(const void* p) {
    uint32_t a;
    asm("{ .reg .u64 t; cvta.to.shared.u64 t, %1; cvt.u32.u64 %0, t; }"
        : "=r"(a) : "l"(p));
    return a;
}

__device__ __forceinline__ void load_A(__half* dst, const __half* __restrict__ src,
                                       int max_rows) {
    int t = threadIdx.x;
#pragma unroll
    for (int i = 0; i < 4; i++) {
        int q = t + 256 * i;
        int row = q >> 3;
        int f4 = q & 7;
        uint32_t daddr;
        asm("{ .reg .u64 tt; cvta.to.shared.u64 tt, %1; cvt.u32.u64 %0, tt; }"
            : "=r"(daddr) : "l"(dst + row * HSTR + f4 * 8));
        int sz = (row < max_rows) ? 16 : 0;
        asm volatile("cp.async.cg.shared.global [%0], [%1], 16, %2;"
                     :: "r"(daddr), "l"(src + (size_t)row * FIN + f4 * 8), "r"(sz));
    }
}

__device__ __forceinline__ void load_B(__half* dst, const __half* __restrict__ src) {
    int t = threadIdx.x;
#pragma unroll
    for (int i = 0; i < 4; i++) {
        int q = t + 256 * i;
        int row = q >> 3;
        int f4 = q & 7;
        uint4 v = *(const uint4*)(src + (size_t)row * FIN + f4 * 8);
        *(uint4*)(dst + row * HSTR + f4 * 8) = v;
    }
}

__global__ __launch_bounds__(256, 2) void k_gemm(const float* __restrict__ bias,
                                                 float* __restrict__ out) {
    extern __shared__ __half sm[];
    __half* As[2] = { sm,                 sm + 2 * 128 * HSTR };
    __half* Bs[2] = { sm + 128 * HSTR,    sm + 3 * 128 * HSTR };

    int tid = threadIdx.x;
    int wid = tid >> 5, lane = tid & 31;
    int wm = wid >> 1, wn = wid & 1;
    int g = lane >> 2, q = lane & 3;
    int b = blockIdx.y;
    int n0 = blockIdx.x * 128;
    int max_rows = NNODES - n0;

    int a_row = lane & 15;
    int a_koff = (lane & 16) ? 8 : 0;
    int b_row = (lane & 7) + ((lane & 16) ? 8 : 0);
    int b_koff = (lane & 8) ? 8 : 0;

    float acc[2][8][4];
#pragma unroll
    for (int mt = 0; mt < 2; mt++)
#pragma unroll
        for (int nt = 0; nt < 8; nt++)
#pragma unroll
            for (int i = 0; i < 4; i++) acc[mt][nt][i] = 0.f;

    const __half* terms[KPOLY];
    terms[0] = g_xh + ((size_t)b * NNODES + n0) * FIN;
#pragma unroll
    for (int kk = 1; kk < KPOLY; kk++)
        terms[kk] = g_Th + (size_t)(kk - 1) * TERM_SZ + ((size_t)b * NNODES + n0) * FIN;

    load_A(As[0], terms[0], max_rows);
    asm volatile("cp.async.commit_group;" ::: "memory");
    load_B(Bs[0], g_Wh);

#pragma unroll
    for (int c = 0; c < KPOLY; c++) {
        int st = c & 1;
        if (c + 1 < KPOLY) {
            load_A(As[st ^ 1], terms[c + 1], max_rows);
            asm volatile("cp.async.commit_group;" ::: "memory");
            load_B(Bs[st ^ 1], g_Wh + (size_t)(c + 1) * FOUT * FIN);
            asm volatile("cp.async.wait_group 1;" ::: "memory");
        } else {
            asm volatile("cp.async.wait_group 0;" ::: "memory");
        }
        __syncthreads();

        uint32_t abase = smem_u32(As[st]);
        uint32_t bbase = smem_u32(Bs[st]);
#pragma unroll
        for (int k16 = 0; k16 < 4; k16++) {
            int kb = k16 * 16;
            uint32_t af[2][4];
#pragma unroll
            for (int mt = 0; mt < 2; mt++) {
                uint32_t addr = abase +
                    2u * ((wm * 32 + mt * 16 + a_row) * HSTR + kb + a_koff);
                ldsm_x4(af[mt][0], af[mt][1], af[mt][2], af[mt][3], addr);
            }
#pragma unroll
            for (int gt = 0; gt < 4; gt++) {
                uint32_t addr = bbase +
                    2u * ((wn * 64 + gt * 16 + b_row) * HSTR + kb + b_koff);
                uint32_t b0, b1, b2, b3;
                ldsm_x4(b0, b1, b2, b3, addr);
                mma_f16(acc[0][2 * gt],     af[0], b0, b1);
                mma_f16(acc[1][2 * gt],     af[1], b0, b1);
                mma_f16(acc[0][2 * gt + 1], af[0], b2, b3);
                mma_f16(acc[1][2 * gt + 1], af[1], b2, b3);
            }
        }
        __syncthreads();
    }

    // epilogue: bias + ReLU, maxpool-4 over fragment rows via 2x shfl, pooled stores
#pragma unroll
    for (int mt = 0; mt < 2; mt++) {
#pragma unroll
        for (int half = 0; half < 2; half++) {
            int nodebase = n0 + wm * 32 + mt * 16 + half * 8 + g;
            float res[8][2];
#pragma unroll
            for (int nt = 0; nt < 8; nt++) {
                int col = wn * 64 + nt * 8 + 2 * q;
                float v0 = fmaxf(acc[mt][nt][half * 2 + 0] + __ldg(bias + col), 0.f);
                float v1 = fmaxf(acc[mt][nt][half * 2 + 1] + __ldg(bias + col + 1), 0.f);
                v0 = fmaxf(v0, __shfl_xor_sync(0xffffffffu, v0, 4));
                v0 = fmaxf(v0, __shfl_xor_sync(0xffffffffu, v0, 8));
                v1 = fmaxf(v1, __shfl_xor_sync(0xffffffffu, v1, 4));
                v1 = fmaxf(v1, __shfl_xor_sync(0xffffffffu, v1, 8));
                res[nt][0] = v0;
                res[nt][1] = v1;
            }
            if ((g & 3) == 0 && nodebase < NNODES) {
                float* op = out + ((size_t)b * NPOOL + (nodebase >> 2)) * FOUT;
#pragma unroll
                for (int nt = 0; nt < 8; nt++) {
                    int col = wn * 64 + nt * 8 + 2 * q;
                    *(float2*)(op + col) = make_float2(res[nt][0], res[nt][1]);
                }
            }
        }
    }
}

// ---------------- launch ---------------------------------------------------------
extern "C" void kernel_launch(void* const* d_in, const int* in_sizes, int n_in,
                              void* d_out, int out_size) {
    const float* x    = (const float*)d_in[0];
    const int*   rows = (const int*)d_in[1];
    const int*   cols = (const int*)d_in[2];
    const float* vals = (const float*)d_in[3];
    const float* W    = (const float*)d_in[4];
    const float* bias = (const float*)d_in[5];
    float* out = (float*)d_out;

    cudaFuncSetAttribute(k_gemm, cudaFuncAttributeMaxDynamicSharedMemorySize, SMEM_BYTES);

    // fused prep (x/W half cvt + edge histogram), scan (+count reset), scatter
    k_prep<<<(int)((H2PAIRS + 255) / 256), 256>>>(x, W, rows);
    k_scan<<<1, 256>>>();
    k_scatter<<<(NEDGES + 255) / 256, 256>>>(rows, cols, vals);

    // Chebyshev recurrence: T1 = L x ; Tk = 2 L T(k-1) - T(k-2)
    k_spmm<<<NNODES, 256>>>(-1, 0, -2);
    k_spmm<<<NNODES, 256>>>( 0, 1, -1);
    k_spmm<<<NNODES, 256>>>( 1, 2,  0);
    k_spmm<<<NNODES, 256>>>( 2, 3,  1);

    // fp16 tensor-core projection + fused epilogue
    dim3 grid((NNODES + 127) / 128, BATCH);
    k_gemm<<<grid, 256, SMEM_BYTES>>>(bias, out);
}